// round 11
// baseline (speedup 1.0000x reference)
#include <cuda_runtime.h>
#include <cstdint>

// VQBlock: x [65536, 256] fp32, dict [256, 1024] fp32.
// out[0..N*D) = q_st = x + (0.5*dict[:,argmin] - x), out[N*D] = 1.25*mean((x-q)^2)
//
// Round 10: FFMA2 GEMM, bit-identical arithmetic to R3 (rel_err 0.0), with
// 2 blocks/SM preserved (48KB smem, <=128 regs), pre-duplicated A operand
// (no packs, direct LDS.128 broadcast frags), cp.async double-buffered
// stages, single barrier per stage.

#define D_DIM 256
#define K_DIM 1024
#define N_ROWS 65536
#define TM 128
#define TN 128
#define KD 16
#define NSTAGES 128   // 8 chunks x 16 depth-stages

#define STAGE_BYTES 24576          // A-dup 16384 + B 8192
#define SMEM_TOTAL  49152          // 2 stages
// post-mainloop aliases inside the same smem
#define OFF_RS    0                // 128*16*4 = 8192
#define OFF_RI    8192             // 8192
#define OFF_SROWK 16384            // 512
#define OFF_SRED  16896            // 2048

__device__ float  g_cnorm[K_DIM];                       // ||dict[:,k]||^2
__device__ float  g_rnorm[N_ROWS];                      // ||x_row||^2
__device__ float  g_dictT[K_DIM * D_DIM];               // [code][d]
__device__ unsigned long long g_xdupT[D_DIM * N_ROWS];  // [d][row] = (v,v)
__device__ double g_sum;

// ---------------------------------------------------------------------------
__device__ __forceinline__ uint32_t smem_u32(const void* p) {
    uint32_t a;
    asm("{ .reg .u64 t; cvta.to.shared.u64 t, %1; cvt.u32.u64 %0, t; }"
        : "=r"(a) : "l"(p));
    return a;
}
__device__ __forceinline__ void cp16(uint32_t dst, const void* src) {
    asm volatile("cp.async.cg.shared.global [%0], [%1], 16;"
                 :: "r"(dst), "l"(src) : "memory");
}
__device__ __forceinline__ void unpack2(unsigned long long p, float& lo, float& hi) {
    unsigned int a, b;
    asm("mov.b64 {%0, %1}, %2;" : "=r"(a), "=r"(b) : "l"(p));
    lo = __uint_as_float(a);
    hi = __uint_as_float(b);
}
__device__ __forceinline__ void ffma2(unsigned long long& acc,
                                      unsigned long long a,
                                      unsigned long long b) {
    asm("fma.rn.f32x2 %0, %1, %2, %0;" : "+l"(acc) : "l"(a), "l"(b));
}

// ---------------------------------------------------------------------------
__global__ void colnorm_kernel(const float* __restrict__ dict) {
    int gt = blockIdx.x * blockDim.x + threadIdx.x;
    if (gt == 0) g_sum = 0.0;
    int warp = gt >> 5;
    int lane = threadIdx.x & 31;
    if (warp >= K_DIM) return;
    double s = 0.0;
    for (int d = lane; d < D_DIM; d += 32) {
        float v = dict[d * K_DIM + warp];
        s += (double)v * v;
        g_dictT[(size_t)warp * D_DIM + d] = v;
    }
#pragma unroll
    for (int o = 16; o > 0; o >>= 1) s += __shfl_xor_sync(0xffffffff, s, o);
    if (lane == 0) g_cnorm[warp] = (float)s;
}

__global__ void rownorm_kernel(const float* __restrict__ x) {
    int warp = (blockIdx.x * blockDim.x + threadIdx.x) >> 5;
    int lane = threadIdx.x & 31;
    if (warp >= N_ROWS) return;
    const float4* p = (const float4*)(x + (size_t)warp * D_DIM);
    float4 a = p[lane];
    float4 b = p[lane + 32];
    double s = (double)a.x * a.x + (double)a.y * a.y
             + (double)a.z * a.z + (double)a.w * a.w
             + (double)b.x * b.x + (double)b.y * b.y
             + (double)b.z * b.z + (double)b.w * b.w;
#pragma unroll
    for (int o = 16; o > 0; o >>= 1) s += __shfl_xor_sync(0xffffffff, s, o);
    if (lane == 0) g_rnorm[warp] = (float)s;
}

// Tiled transpose + duplicate: g_xdupT[d][row] = (x[row][d], x[row][d]).
// 32x32 tiles, 256 threads (32x8).
__global__ void xdup_kernel(const float* __restrict__ x) {
    __shared__ float t[32][33];
    int rt = blockIdx.x;              // row-tile (2048)
    int dt = blockIdx.y;              // d-tile (8)
    int lx = threadIdx.x & 31;
    int ly = threadIdx.x >> 5;        // 0..7
#pragma unroll
    for (int i = 0; i < 4; i++) {
        int r = rt * 32 + ly + i * 8;
        t[ly + i * 8][lx] = x[(size_t)r * D_DIM + dt * 32 + lx];
    }
    __syncthreads();
#pragma unroll
    for (int i = 0; i < 4; i++) {
        int d = dt * 32 + ly + i * 8;
        float v = t[lx][ly + i * 8];
        unsigned int b = __float_as_uint(v);
        unsigned long long p;
        asm("mov.b64 %0, {%1, %2};" : "=l"(p) : "r"(b), "r"(b));
        g_xdupT[(size_t)d * N_ROWS + rt * 32 + lx] = p;
    }
}

// ---------------------------------------------------------------------------
// 256 threads, 2 blocks/SM, one 128-row tile per block, 8 chunks of 128 codes.
// 8x8 microtile per thread as 8x4 FFMA2 pairs.
__global__ __launch_bounds__(256, 2) void vq_main(const float* __restrict__ x,
                                                  const float* __restrict__ dict,
                                                  float* __restrict__ out) {
    extern __shared__ char smem[];
    const uint32_t smu = smem_u32(smem);
    const int tid = threadIdx.x;
    const int tx = tid & 15;
    const int ty = tid >> 4;
    const int row0 = blockIdx.x * TM;

    // stage issue: A-dup 16 dd x 128 rows (u64) + B 16 dd x 128 cols (f32)
    auto issue = [&](int g) {
        const int chunk = (g >> 4) * TN;
        const int d0 = (g & 15) * KD;
        const uint32_t sbase = smu + (uint32_t)(g & 1) * STAGE_BYTES;
        // A: 1024 cp16 -> 4 per thread. [dd][row] u64, 16B = 2 rows.
#pragma unroll
        for (int i = 0; i < 4; i++) {
            int q = i * 256 + tid;
            int dd = q >> 6;
            int rp = q & 63;
            cp16(sbase + (uint32_t)(dd * 1024 + rp * 16),
                 g_xdupT + (size_t)(d0 + dd) * N_ROWS + row0 + rp * 2);
        }
        // B: 512 cp16 -> 2 per thread. [dd][col] f32.
        {
            int brow = tid >> 4;
            int bc = (tid & 15) * 8;
            const float* src = dict + (size_t)(d0 + brow) * K_DIM + chunk + bc;
            uint32_t dst = sbase + 16384 + (uint32_t)(brow * 512 + bc * 4);
            cp16(dst, src);
            cp16(dst + 16, src + 4);
        }
        asm volatile("cp.async.commit_group;" ::: "memory");
    };

    float best[8];
    int   bestk[8];
    float r8[8];
#pragma unroll
    for (int i = 0; i < 8; i++) {
        best[i] = 3.4e38f;
        bestk[i] = 0;
        r8[i] = g_rnorm[row0 + ty * 8 + i];
    }

    issue(0);

    unsigned long long acc2[8][4];

    for (int g = 0; g < NSTAGES; g++) {
        if (g + 1 < NSTAGES) {
            issue(g + 1);
            asm volatile("cp.async.wait_group 1;" ::: "memory");
        } else {
            asm volatile("cp.async.wait_group 0;" ::: "memory");
        }
        __syncthreads();

        if ((g & 15) == 0) {
#pragma unroll
            for (int i = 0; i < 8; i++)
#pragma unroll
                for (int j = 0; j < 4; j++) acc2[i][j] = 0ull;
        }

        const char* sbase = smem + (g & 1) * STAGE_BYTES;
        const unsigned long long* Adup =
            (const unsigned long long*)sbase;          // [dd][128] u64
        const float* Bs = (const float*)(sbase + 16384); // [dd][128] f32

#pragma unroll
        for (int dd = 0; dd < KD; dd++) {
            unsigned long long a2[8];
            *(ulonglong2*)&a2[0] = *(const ulonglong2*)&Adup[dd * 128 + ty * 8];
            *(ulonglong2*)&a2[2] = *(const ulonglong2*)&Adup[dd * 128 + ty * 8 + 2];
            *(ulonglong2*)&a2[4] = *(const ulonglong2*)&Adup[dd * 128 + ty * 8 + 4];
            *(ulonglong2*)&a2[6] = *(const ulonglong2*)&Adup[dd * 128 + ty * 8 + 6];
            unsigned long long b2[4];
            *(ulonglong2*)&b2[0] = *(const ulonglong2*)&Bs[dd * 128 + tx * 8];
            *(ulonglong2*)&b2[2] = *(const ulonglong2*)&Bs[dd * 128 + tx * 8 + 4];
#pragma unroll
            for (int i = 0; i < 8; i++)
#pragma unroll
                for (int j = 0; j < 4; j++)
                    ffma2(acc2[i][j], a2[i], b2[j]);
        }
        __syncthreads();   // consumed before next stage overwrites this buffer

        if ((g & 15) == 15) {
            // chunk epilogue: dist = fl(fl(r + c) - 2*sim), first-index argmin
            const int chunk = (g >> 4) * TN;
#pragma unroll
            for (int j = 0; j < 4; j++) {
                int k0 = chunk + tx * 8 + 2 * j;
                float c0 = g_cnorm[k0];
                float c1 = g_cnorm[k0 + 1];
#pragma unroll
                for (int i = 0; i < 8; i++) {
                    float s0, s1;
                    unpack2(acc2[i][j], s0, s1);
                    float d0v = __fsub_rn(__fadd_rn(r8[i], c0),
                                          __fmul_rn(2.0f, s0));
                    float d1v = __fsub_rn(__fadd_rn(r8[i], c1),
                                          __fmul_rn(2.0f, s1));
                    if (d0v < best[i]) { best[i] = d0v; bestk[i] = k0; }
                    if (d1v < best[i]) { best[i] = d1v; bestk[i] = k0 + 1; }
                }
            }
        }
    }

    // ---- cross-thread argmin reduce (aliases stage smem) ----
    float* rs = (float*)(smem + OFF_RS);
    int*   ri = (int*)(smem + OFF_RI);
    int*   srow_k = (int*)(smem + OFF_SROWK);
    __syncthreads();
#pragma unroll
    for (int i = 0; i < 8; i++) {
        rs[(ty * 8 + i) * 16 + tx] = best[i];
        ri[(ty * 8 + i) * 16 + tx] = bestk[i];
    }
    __syncthreads();
    if (tid < TM) {
        float b = rs[tid * 16];
        int  bk = ri[tid * 16];
#pragma unroll
        for (int t = 1; t < 16; t++) {
            float v = rs[tid * 16 + t];
            int  vk = ri[tid * 16 + t];
            if (v < b || (v == b && vk < bk)) { b = v; bk = vk; }
        }
        srow_k[tid] = bk;
    }
    __syncthreads();

    // ---- output q_st + loss ----
    double lsum = 0.0;
    for (int e = tid; e < TM * D_DIM; e += 256) {
        int r = e >> 8;
        int d = e & 255;
        int k = srow_k[r];
        float qv = 0.5f * g_dictT[(size_t)k * D_DIM + d];
        float xv = x[(size_t)(row0 + r) * D_DIM + d];
        out[(size_t)(row0 + r) * D_DIM + d] = __fadd_rn(xv, __fsub_rn(qv, xv));
        float df = xv - qv;
        lsum += (double)df * (double)df;
    }
    double* sred = (double*)(smem + OFF_SRED);
    sred[tid] = lsum;
    __syncthreads();
    for (int s = 128; s > 0; s >>= 1) {
        if (tid < s) sred[tid] += sred[tid + s];
        __syncthreads();
    }
    if (tid == 0) atomicAdd(&g_sum, sred[0]);
}

// ---------------------------------------------------------------------------
__global__ void finalize_kernel(float* out, long long total, int loss_idx) {
    out[loss_idx] = (float)(1.25 * g_sum / (double)total);
}

// ---------------------------------------------------------------------------
extern "C" void kernel_launch(void* const* d_in, const int* in_sizes, int n_in,
                              void* d_out, int out_size) {
    const float* x    = (const float*)d_in[0];
    const float* dict = (const float*)d_in[1];
    float* out = (float*)d_out;

    int Nel = in_sizes[0];     // 16777216
    int N   = Nel / D_DIM;     // 65536

    cudaFuncSetAttribute(vq_main, cudaFuncAttributeMaxDynamicSharedMemorySize,
                         SMEM_TOTAL);

    colnorm_kernel<<<(K_DIM * 32 + 255) / 256, 256>>>(dict);
    rownorm_kernel<<<(N * 32 + 255) / 256, 256>>>(x);
    {
        dim3 gridT(N / 32, D_DIM / 32);
        xdup_kernel<<<gridT, 256>>>(x);
    }
    vq_main<<<N / TM, 256, SMEM_TOTAL>>>(x, dict, out);
    if (out_size > Nel) {
        finalize_kernel<<<1, 1>>>(out, (long long)Nel, out_size - 1);
    }
}